// round 13
// baseline (speedup 1.0000x reference)
#include <cuda_runtime.h>
#include <cstdint>

#define B_ 64
#define S_ 512
#define H_ 1024
#define V_ 128
#define THREADS_A 256
#define HB (H_ * B_)   /* 65536 floats per time slot, layout [h][b] */
#define RPAD 516       /* red plane stride (floats) */
#define KBLK 272       /* padded kg-block: 16 rows x 16 floats + 16 pad */
#define SUBT (16 * KBLK) /* floats per sub-tile: 4352 */

// Hidden-state history, layout (slot, h, b); slot 0 = initial h (transposed),
// slot t+1 = hidden after step t.
__device__ __align__(16) float g_hid[(size_t)(S_ + 1) * HB];
// One full-barrier counter per batch-group (4 pools of 32 CTAs), 128B apart.
__device__ unsigned int g_cntb[4 * 32];
__device__ float g_dummy;

// ---------------------------------------------------------------------------
__global__ void rnn_init(const float* __restrict__ h0) {
    int i = blockIdx.x * blockDim.x + threadIdx.x;
    if (i < 4 * 32) g_cntb[i] = 0u;
    if (i < HB) {
        int b = i >> 10;        // i = b*1024 + h
        int hh = i & 1023;
        g_hid[(size_t)hh * B_ + b] = h0[i];
    }
}
// Distinct tiny kernels keep rnn_recur in ncu's profiled slot (offset-2).
__global__ void rnn_dmy1(const float* __restrict__ h0) {
    if (threadIdx.x == 0 && blockIdx.x == 0) g_dummy = h0[0];
}
__global__ void rnn_dmy2(const float* __restrict__ h0) {
    if (threadIdx.x == 0 && blockIdx.x == 0) g_dummy = h0[1];
}

// ---------------------------------------------------------------------------
// cp.async staging of one k-sub-tile of h (256 rows x 16 batches = 16 KB)
// into the kg-block-padded smem layout: row k at (k>>4)*KBLK + (k&15)*16.
// ---------------------------------------------------------------------------
__device__ __forceinline__ void stage_sub(uint32_t dst_s, const float* src_base, int tid) {
#pragma unroll
    for (int j = 0; j < 4; ++j) {
        int c = tid + j * THREADS_A;               // 0..1023 16B chunks
        int row = c >> 2, q = c & 3;
        uint32_t doff = (uint32_t)(((row >> 4) * KBLK + (row & 15) * 16 + q * 4) * 4);
        asm volatile("cp.async.cg.shared.global [%0], [%1], 16;\n"
                     :: "r"(dst_s + doff),
                        "l"(src_base + (size_t)row * B_ + q * 4)
                     : "memory");
    }
}

// ---------------------------------------------------------------------------
// Persistent recurrence. 128 CTAs x 256 threads. CTA (bg, cg) owns
// batches [16bg,16bg+16) x cols [32cg,32cg+32). Four decoupled pools of 32
// CTAs (per bg), R1-proven full-barrier idiom. Thread tile 8b x 4c, k-split
// 16. NEW: h_sm kg-blocks padded +64B so the warp's two k-groups occupy
// disjoint bank halves — every h LDS.128 is conflict-free (6 -> 4 wf/k/warp).
// ---------------------------------------------------------------------------
__global__ __launch_bounds__(THREADS_A, 1) void rnn_recur(
    const int* __restrict__ x, const float* __restrict__ W_xh,
    const float* __restrict__ W_hh, const float* __restrict__ b_h,
    float* __restrict__ hfinal_out)
{
    extern __shared__ float sm[];
    float* h_sm   = sm;                              // 4 * SUBT floats     ~68KB
    float* red_sm = sm;                              // ALIAS: 16*RPAD = 33KB
    float* w_sm   = h_sm + 4 * SUBT;                 // 1024 * 32           128KB
    float* wxh_sm = w_sm + H_ * 32;                  // 128 * 32             16KB
    float* bh_sm  = wxh_sm + V_ * 32;                // 32
    int*   x_sm   = (int*)(bh_sm + 32);              // 16

    const int tid   = threadIdx.x;
    const int bg    = blockIdx.x >> 5;               // batch group 0..3
    const int cg    = blockIdx.x & 31;               // col group   0..31
    const int cbase = cg * 32;
    const int boff  = bg * 16;

    // One-time preload: W_hh slice k-major [k][32], W_xh slice, bias.
    for (int i = tid; i < H_ * 32; i += THREADS_A) {
        int k = i >> 5, c = i & 31;
        w_sm[i] = W_hh[(size_t)k * H_ + cbase + c];
    }
    for (int i = tid; i < V_ * 32; i += THREADS_A) {
        int v = i >> 5, c = i & 31;
        wxh_sm[i] = W_xh[(size_t)v * H_ + cbase + c];
    }
    if (tid < 32) bh_sm[tid] = b_h[cbase + tid];
    __syncthreads();

    const int kg = tid >> 4;        // k-split group 0..15 (64 k each)
    const int gb = (tid >> 3) & 1;  // batch half: 8 batches
    const int gc = tid & 7;         // col quad: 4 cols
    const int b0 = gb * 8;
    const int c0 = gc * 4;

    // Parallel-tail mapping (proven shape): 2 outputs per thread.
    const int tcol = tid >> 3;            // 0..31
    const int tb   = (tid & 7) * 2;       // 0,2,..,14

    uint32_t hs_base = (uint32_t)__cvta_generic_to_shared(h_sm);

    for (int t = 0; t < S_; ++t) {
        const float* hsrc = g_hid + (size_t)t * HB + boff;
        if (tid < 16) x_sm[tid] = x[(size_t)(boff + tid) * S_ + t];

        float acc[4][8];
#pragma unroll
        for (int i = 0; i < 4; ++i)
#pragma unroll
            for (int j = 0; j < 8; ++j) acc[i][j] = 0.f;

        // Stage all 4 sub-tiles up-front, one commit group each.
#pragma unroll
        for (int s = 0; s < 4; ++s) {
            stage_sub(hs_base + (uint32_t)(s * SUBT * 4),
                      hsrc + (size_t)(s * 256) * B_, tid);
            asm volatile("cp.async.commit_group;\n" ::: "memory");
        }

#pragma unroll
        for (int s = 0; s < 4; ++s) {
            if (s == 0)      asm volatile("cp.async.wait_group 3;\n" ::: "memory");
            else if (s == 1) asm volatile("cp.async.wait_group 2;\n" ::: "memory");
            else if (s == 2) asm volatile("cp.async.wait_group 1;\n" ::: "memory");
            else             asm volatile("cp.async.wait_group 0;\n" ::: "memory");
            __syncthreads();

            // This thread's 16 k of sub-tile s live in its padded kg block.
            const float* hq = h_sm + s * SUBT + kg * KBLK + b0;
            const float* wq = w_sm + (s * 256 + kg * 16) * 32 + c0;
#pragma unroll
            for (int j = 0; j < 16; ++j) {
                float4 wv = *(const float4*)(wq);
                float4 hA = *(const float4*)(hq);
                float4 hB = *(const float4*)(hq + 4);
#pragma unroll
                for (int cc = 0; cc < 4; ++cc) {
                    float w = (&wv.x)[cc];
                    acc[cc][0] += hA.x * w; acc[cc][1] += hA.y * w;
                    acc[cc][2] += hA.z * w; acc[cc][3] += hA.w * w;
                    acc[cc][4] += hB.x * w; acc[cc][5] += hB.y * w;
                    acc[cc][6] += hB.z * w; acc[cc][7] += hB.w * w;
                }
                hq += 16;
                wq += 32;
            }
        }

        // red_sm aliases h_sm: wait for all h reads to finish first.
        __syncthreads();
        {
            float* rp = red_sm + kg * RPAD + c0 * 16 + b0;
#pragma unroll
            for (int cc = 0; cc < 4; ++cc) {
                *(float4*)(rp + cc * 16)     = make_float4(acc[cc][0], acc[cc][1],
                                                           acc[cc][2], acc[cc][3]);
                *(float4*)(rp + cc * 16 + 4) = make_float4(acc[cc][4], acc[cc][5],
                                                           acc[cc][6], acc[cc][7]);
            }
        }
        __syncthreads();

        // Parallel tail: reduce 16 partials for 2 outputs, tanh, store h[t+1].
        {
            float s0 = 0.f, s1 = 0.f;
#pragma unroll
            for (int kq = 0; kq < 16; ++kq) {
                float2 v = *(const float2*)&red_sm[kq * RPAD + tcol * 16 + tb];
                s0 += v.x; s1 += v.y;
            }
            float wb0 = wxh_sm[x_sm[tb] * 32 + tcol];
            float wb1 = wxh_sm[x_sm[tb + 1] * 32 + tcol];
            float v0 = tanhf(s0 + wb0 + bh_sm[tcol]);
            float v1 = tanhf(s1 + wb1 + bh_sm[tcol]);
            *(float2*)&g_hid[(size_t)(t + 1) * HB +
                             (size_t)(cbase + tcol) * B_ + boff + tb] =
                make_float2(v0, v1);
            if (t == S_ - 1) {
                hfinal_out[(size_t)(boff + tb) * H_ + cbase + tcol]     = v0;
                hfinal_out[(size_t)(boff + tb + 1) * H_ + cbase + tcol] = v1;
            }
        }

        // R1-proven full barrier, among this batch-group's 32 CTAs only.
        __threadfence();
        __syncthreads();
        if (tid == 0) {
            unsigned target = (unsigned)(t + 1) * 32u;
            atomicAdd(&g_cntb[bg * 32], 1u);
            volatile unsigned* vc = &g_cntb[bg * 32];
            while ((int)(*vc - target) < 0) { }
            __threadfence();
        }
        __syncthreads();
    }
}

// ---------------------------------------------------------------------------
// logits = hidden @ W_out + b_out.  M=32768 (m = t*64+b), N=128, K=1024.
// A read from g_hid (t+1, k, b). 256 CTAs, 128x128 tile, 8x8 micro. (proven)
// ---------------------------------------------------------------------------
__global__ __launch_bounds__(256) void rnn_logits(
    const float* __restrict__ W_out, const float* __restrict__ b_out,
    float* __restrict__ out)
{
    __shared__ float a_sm[32][128];
    __shared__ float b_sm[32][128];
    const int tid = threadIdx.x;
    const int M0  = blockIdx.x * 128;
    const int t0  = M0 >> 6;
    const int tx  = tid & 15, ty = tid >> 4;

    float acc[8][8];
#pragma unroll
    for (int i = 0; i < 8; ++i)
#pragma unroll
        for (int j = 0; j < 8; ++j) acc[i][j] = 0.f;

    for (int kt = 0; kt < 32; ++kt) {
        int k0 = kt * 32;
#pragma unroll
        for (int j2 = 0; j2 < 4; ++j2) {
            int q = tid + j2 * 256;
            int k = q >> 5;
            int m = (q & 31) << 2;
            const float* asrc = g_hid + (size_t)(t0 + (m >> 6) + 1) * HB +
                                (size_t)(k0 + k) * B_ + (m & 63);
            *(float4*)&a_sm[k][m] = *(const float4*)asrc;
            *(float4*)&b_sm[k][m] = *(const float4*)&W_out[(size_t)(k0 + k) * V_ + m];
        }
        __syncthreads();
#pragma unroll
        for (int k = 0; k < 32; ++k) {
            float4 a0 = *(float4*)&a_sm[k][ty * 8];
            float4 a1 = *(float4*)&a_sm[k][ty * 8 + 4];
            float4 w0 = *(float4*)&b_sm[k][tx * 8];
            float4 w1 = *(float4*)&b_sm[k][tx * 8 + 4];
            float av[8] = {a0.x, a0.y, a0.z, a0.w, a1.x, a1.y, a1.z, a1.w};
            float bv[8] = {w0.x, w0.y, w0.z, w0.w, w1.x, w1.y, w1.z, w1.w};
#pragma unroll
            for (int i = 0; i < 8; ++i)
#pragma unroll
                for (int j = 0; j < 8; ++j) acc[i][j] += av[i] * bv[j];
        }
        __syncthreads();
    }

    float bo[8];
#pragma unroll
    for (int j = 0; j < 8; ++j) bo[j] = b_out[tx * 8 + j];
#pragma unroll
    for (int i = 0; i < 8; ++i) {
        int mg = M0 + ty * 8 + i;
        int tt = mg >> 6, b = mg & 63;
        float* op = out + ((size_t)b * S_ + tt) * V_ + tx * 8;
        *(float4*)op       = make_float4(acc[i][0] + bo[0], acc[i][1] + bo[1],
                                         acc[i][2] + bo[2], acc[i][3] + bo[3]);
        *(float4*)(op + 4) = make_float4(acc[i][4] + bo[4], acc[i][5] + bo[5],
                                         acc[i][6] + bo[6], acc[i][7] + bo[7]);
    }
}

// ---------------------------------------------------------------------------
extern "C" void kernel_launch(void* const* d_in, const int* in_sizes, int n_in,
                              void* d_out, int out_size) {
    (void)in_sizes; (void)n_in; (void)out_size;
    const int*   x     = (const int*)  d_in[0];
    const float* h0    = (const float*)d_in[1];
    const float* W_xh  = (const float*)d_in[2];
    const float* W_hh  = (const float*)d_in[3];
    const float* b_h   = (const float*)d_in[4];
    const float* W_out = (const float*)d_in[5];
    const float* b_out = (const float*)d_in[6];
    float* out = (float*)d_out;

    const int SMEM_A = (4 * SUBT + H_ * 32 + V_ * 32 + 32) * (int)sizeof(float)
                       + 16 * (int)sizeof(int);
    cudaFuncSetAttribute(rnn_recur, cudaFuncAttributeMaxDynamicSharedMemorySize, SMEM_A);

    // Slot map (proven): 0=init, 1=dmy1, 2=dmy2, 3=recur (profiled), 4=logits.
    rnn_init<<<(HB + 255) / 256, 256>>>(h0);
    rnn_dmy1<<<1, 32>>>(h0);
    rnn_dmy2<<<1, 32>>>(h0);
    rnn_recur<<<128, THREADS_A, SMEM_A>>>(x, W_xh, W_hh, b_h,
                                          out + (size_t)B_ * S_ * V_);
    rnn_logits<<<(B_ * S_) / 128, 256>>>(W_out, b_out, out);
}

// round 14
// speedup vs baseline: 1.0602x; 1.0602x over previous
#include <cuda_runtime.h>
#include <cstdint>

typedef unsigned long long ull;

#define B_ 64
#define S_ 512
#define H_ 1024
#define V_ 128
#define THREADS_A 256
#define HB (H_ * B_)   /* 65536 floats per time slot, layout [h][b] */
#define RPAD 516       /* red plane stride (floats) */

// Hidden-state history, layout (slot, h, b); slot 0 = initial h (transposed),
// slot t+1 = hidden after step t.
__device__ __align__(16) float g_hid[(size_t)(S_ + 1) * HB];
// One full-barrier counter per batch-group (4 pools of 32 CTAs), 128B apart.
__device__ unsigned int g_cntb[4 * 32];
__device__ float g_dummy;

__device__ __forceinline__ ull dup2(float v) {
    ull r; asm("mov.b64 %0, {%1, %1};" : "=l"(r) : "f"(v)); return r;
}
#define FMA2(d, a, b) asm("fma.rn.f32x2 %0, %1, %2, %0;" : "+l"(d) : "l"(a), "l"(b))

// ---------------------------------------------------------------------------
__global__ void rnn_init(const float* __restrict__ h0) {
    int i = blockIdx.x * blockDim.x + threadIdx.x;
    if (i < 4 * 32) g_cntb[i] = 0u;
    if (i < HB) {
        int b = i >> 10;        // i = b*1024 + h
        int hh = i & 1023;
        g_hid[(size_t)hh * B_ + b] = h0[i];
    }
}
// Distinct tiny kernels keep rnn_recur in ncu's profiled slot (offset-2).
__global__ void rnn_dmy1(const float* __restrict__ h0) {
    if (threadIdx.x == 0 && blockIdx.x == 0) g_dummy = h0[0];
}
__global__ void rnn_dmy2(const float* __restrict__ h0) {
    if (threadIdx.x == 0 && blockIdx.x == 0) g_dummy = h0[1];
}

// ---------------------------------------------------------------------------
// cp.async staging of one k-sub-tile of h: 256 k-rows x 16 batches = 16 KB.
// (R12 layout: contiguous, unpadded.)
// ---------------------------------------------------------------------------
__device__ __forceinline__ void stage_sub(uint32_t dst_s, const float* src_base, int tid) {
#pragma unroll
    for (int j = 0; j < 4; ++j) {
        int c = tid + j * THREADS_A;               // 0..1023 16B chunks
        int row = c >> 2, q = c & 3;
        asm volatile("cp.async.cg.shared.global [%0], [%1], 16;\n"
                     :: "r"(dst_s + (uint32_t)c * 16u),
                        "l"(src_base + (size_t)row * B_ + q * 4)
                     : "memory");
    }
}

// ---------------------------------------------------------------------------
// Persistent recurrence. 128 CTAs x 256 threads. CTA (bg, cg) owns
// batches [16bg,16bg+16) x cols [32cg,32cg+32). Four decoupled pools of 32
// CTAs (per bg), R1-proven full-barrier idiom. Thread tile 8b x 4c, k-split
// 16 (R12-proven). NEW: packed fma.rn.f32x2 over batch pairs — 16 FFMA2
// instead of 32 FFMA per k; w kept compact in SMEM and duplicated into
// registers per k (SMEM bytes per FMA unchanged).
// ---------------------------------------------------------------------------
__global__ __launch_bounds__(THREADS_A, 1) void rnn_recur(
    const int* __restrict__ x, const float* __restrict__ W_xh,
    const float* __restrict__ W_hh, const float* __restrict__ b_h,
    float* __restrict__ hfinal_out)
{
    extern __shared__ float sm[];
    float* h_sm   = sm;                              // 4 * 256 * 16 floats  64KB
    float* red_sm = sm;                              // ALIAS: 16*RPAD = 33KB
    float* w_sm   = h_sm + 4 * 256 * 16;             // 1024 * 32           128KB
    float* wxh_sm = w_sm + H_ * 32;                  // 128 * 32             16KB
    float* bh_sm  = wxh_sm + V_ * 32;                // 32
    int*   x_sm   = (int*)(bh_sm + 32);              // 16

    const int tid   = threadIdx.x;
    const int bg    = blockIdx.x >> 5;               // batch group 0..3
    const int cg    = blockIdx.x & 31;               // col group   0..31
    const int cbase = cg * 32;
    const int boff  = bg * 16;

    // One-time preload: W_hh slice k-major [k][32], W_xh slice, bias.
    for (int i = tid; i < H_ * 32; i += THREADS_A) {
        int k = i >> 5, c = i & 31;
        w_sm[i] = W_hh[(size_t)k * H_ + cbase + c];
    }
    for (int i = tid; i < V_ * 32; i += THREADS_A) {
        int v = i >> 5, c = i & 31;
        wxh_sm[i] = W_xh[(size_t)v * H_ + cbase + c];
    }
    if (tid < 32) bh_sm[tid] = b_h[cbase + tid];
    __syncthreads();

    const int kg = tid >> 4;        // k-split group 0..15 (64 k each)
    const int gb = (tid >> 3) & 1;  // batch half: 8 batches
    const int gc = tid & 7;         // col quad: 4 cols
    const int b0 = gb * 8;
    const int c0 = gc * 4;

    // Parallel-tail mapping (proven shape): 2 outputs per thread.
    const int tcol = tid >> 3;            // 0..31
    const int tb   = (tid & 7) * 2;       // 0,2,..,14

    uint32_t hs_base = (uint32_t)__cvta_generic_to_shared(h_sm);

    for (int t = 0; t < S_; ++t) {
        const float* hsrc = g_hid + (size_t)t * HB + boff;
        if (tid < 16) x_sm[tid] = x[(size_t)(boff + tid) * S_ + t];

        // acc[cc][p]: col cc (c0+cc), batch pair p -> batches (b0+2p, b0+2p+1)
        ull acc[4][4];
#pragma unroll
        for (int i = 0; i < 4; ++i)
#pragma unroll
            for (int j = 0; j < 4; ++j) acc[i][j] = 0ull;

        // Stage all 4 sub-tiles up-front, one commit group each.
#pragma unroll
        for (int s = 0; s < 4; ++s) {
            stage_sub(hs_base + (uint32_t)(s * 256 * 16 * 4),
                      hsrc + (size_t)(s * 256) * B_, tid);
            asm volatile("cp.async.commit_group;\n" ::: "memory");
        }

#pragma unroll
        for (int s = 0; s < 4; ++s) {
            if (s == 0)      asm volatile("cp.async.wait_group 3;\n" ::: "memory");
            else if (s == 1) asm volatile("cp.async.wait_group 2;\n" ::: "memory");
            else if (s == 2) asm volatile("cp.async.wait_group 1;\n" ::: "memory");
            else             asm volatile("cp.async.wait_group 0;\n" ::: "memory");
            __syncthreads();

            // This thread's 16 k of sub-tile s: local k = kg*16 + j.
            const float* hq = h_sm + s * 4096 + (kg * 16) * 16 + b0;
            const float* wq = w_sm + (s * 256 + kg * 16) * 32 + c0;
#pragma unroll
            for (int j = 0; j < 16; ++j) {
                float4 wv = *(const float4*)(wq);
                ull wd0 = dup2(wv.x), wd1 = dup2(wv.y);
                ull wd2 = dup2(wv.z), wd3 = dup2(wv.w);
                ulonglong2 hA = *(const ulonglong2*)(hq);      // b0..b0+3
                ulonglong2 hB = *(const ulonglong2*)(hq + 4);  // b0+4..b0+7
                FMA2(acc[0][0], hA.x, wd0); FMA2(acc[0][1], hA.y, wd0);
                FMA2(acc[0][2], hB.x, wd0); FMA2(acc[0][3], hB.y, wd0);
                FMA2(acc[1][0], hA.x, wd1); FMA2(acc[1][1], hA.y, wd1);
                FMA2(acc[1][2], hB.x, wd1); FMA2(acc[1][3], hB.y, wd1);
                FMA2(acc[2][0], hA.x, wd2); FMA2(acc[2][1], hA.y, wd2);
                FMA2(acc[2][2], hB.x, wd2); FMA2(acc[2][3], hB.y, wd2);
                FMA2(acc[3][0], hA.x, wd3); FMA2(acc[3][1], hA.y, wd3);
                FMA2(acc[3][2], hB.x, wd3); FMA2(acc[3][3], hB.y, wd3);
                hq += 16;
                wq += 32;
            }
        }

        // red_sm aliases h_sm: wait for all h reads to finish first.
        __syncthreads();
        {
            // Packed pairs are bit-identical to the old float order.
            float* rp = red_sm + kg * RPAD + c0 * 16 + b0;
#pragma unroll
            for (int cc = 0; cc < 4; ++cc) {
                ulonglong2 v0; v0.x = acc[cc][0]; v0.y = acc[cc][1];
                ulonglong2 v1; v1.x = acc[cc][2]; v1.y = acc[cc][3];
                *(ulonglong2*)(rp + cc * 16)     = v0;
                *(ulonglong2*)(rp + cc * 16 + 4) = v1;
            }
        }
        __syncthreads();

        // Parallel tail: reduce 16 partials for 2 outputs, tanh, store h[t+1].
        {
            float s0 = 0.f, s1 = 0.f;
#pragma unroll
            for (int kq = 0; kq < 16; ++kq) {
                float2 v = *(const float2*)&red_sm[kq * RPAD + tcol * 16 + tb];
                s0 += v.x; s1 += v.y;
            }
            float wb0 = wxh_sm[x_sm[tb] * 32 + tcol];
            float wb1 = wxh_sm[x_sm[tb + 1] * 32 + tcol];
            float v0 = tanhf(s0 + wb0 + bh_sm[tcol]);
            float v1 = tanhf(s1 + wb1 + bh_sm[tcol]);
            *(float2*)&g_hid[(size_t)(t + 1) * HB +
                             (size_t)(cbase + tcol) * B_ + boff + tb] =
                make_float2(v0, v1);
            if (t == S_ - 1) {
                hfinal_out[(size_t)(boff + tb) * H_ + cbase + tcol]     = v0;
                hfinal_out[(size_t)(boff + tb + 1) * H_ + cbase + tcol] = v1;
            }
        }

        // R1-proven full barrier, among this batch-group's 32 CTAs only.
        __threadfence();
        __syncthreads();
        if (tid == 0) {
            unsigned target = (unsigned)(t + 1) * 32u;
            atomicAdd(&g_cntb[bg * 32], 1u);
            volatile unsigned* vc = &g_cntb[bg * 32];
            while ((int)(*vc - target) < 0) { }
            __threadfence();
        }
        __syncthreads();
    }
}

// ---------------------------------------------------------------------------
// logits = hidden @ W_out + b_out.  M=32768 (m = t*64+b), N=128, K=1024.
// A read from g_hid (t+1, k, b). 256 CTAs, 128x128 tile, 8x8 micro. (proven)
// ---------------------------------------------------------------------------
__global__ __launch_bounds__(256) void rnn_logits(
    const float* __restrict__ W_out, const float* __restrict__ b_out,
    float* __restrict__ out)
{
    __shared__ float a_sm[32][128];
    __shared__ float b_sm[32][128];
    const int tid = threadIdx.x;
    const int M0  = blockIdx.x * 128;
    const int t0  = M0 >> 6;
    const int tx  = tid & 15, ty = tid >> 4;

    float acc[8][8];
#pragma unroll
    for (int i = 0; i < 8; ++i)
#pragma unroll
        for (int j = 0; j < 8; ++j) acc[i][j] = 0.f;

    for (int kt = 0; kt < 32; ++kt) {
        int k0 = kt * 32;
#pragma unroll
        for (int j2 = 0; j2 < 4; ++j2) {
            int q = tid + j2 * 256;
            int k = q >> 5;
            int m = (q & 31) << 2;
            const float* asrc = g_hid + (size_t)(t0 + (m >> 6) + 1) * HB +
                                (size_t)(k0 + k) * B_ + (m & 63);
            *(float4*)&a_sm[k][m] = *(const float4*)asrc;
            *(float4*)&b_sm[k][m] = *(const float4*)&W_out[(size_t)(k0 + k) * V_ + m];
        }
        __syncthreads();
#pragma unroll
        for (int k = 0; k < 32; ++k) {
            float4 a0 = *(float4*)&a_sm[k][ty * 8];
            float4 a1 = *(float4*)&a_sm[k][ty * 8 + 4];
            float4 w0 = *(float4*)&b_sm[k][tx * 8];
            float4 w1 = *(float4*)&b_sm[k][tx * 8 + 4];
            float av[8] = {a0.x, a0.y, a0.z, a0.w, a1.x, a1.y, a1.z, a1.w};
            float bv[8] = {w0.x, w0.y, w0.z, w0.w, w1.x, w1.y, w1.z, w1.w};
#pragma unroll
            for (int i = 0; i < 8; ++i)
#pragma unroll
                for (int j = 0; j < 8; ++j) acc[i][j] += av[i] * bv[j];
        }
        __syncthreads();
    }

    float bo[8];
#pragma unroll
    for (int j = 0; j < 8; ++j) bo[j] = b_out[tx * 8 + j];
#pragma unroll
    for (int i = 0; i < 8; ++i) {
        int mg = M0 + ty * 8 + i;
        int tt = mg >> 6, b = mg & 63;
        float* op = out + ((size_t)b * S_ + tt) * V_ + tx * 8;
        *(float4*)op       = make_float4(acc[i][0] + bo[0], acc[i][1] + bo[1],
                                         acc[i][2] + bo[2], acc[i][3] + bo[3]);
        *(float4*)(op + 4) = make_float4(acc[i][4] + bo[4], acc[i][5] + bo[5],
                                         acc[i][6] + bo[6], acc[i][7] + bo[7]);
    }
}

// ---------------------------------------------------------------------------
extern "C" void kernel_launch(void* const* d_in, const int* in_sizes, int n_in,
                              void* d_out, int out_size) {
    (void)in_sizes; (void)n_in; (void)out_size;
    const int*   x     = (const int*)  d_in[0];
    const float* h0    = (const float*)d_in[1];
    const float* W_xh  = (const float*)d_in[2];
    const float* W_hh  = (const float*)d_in[3];
    const float* b_h   = (const float*)d_in[4];
    const float* W_out = (const float*)d_in[5];
    const float* b_out = (const float*)d_in[6];
    float* out = (float*)d_out;

    const int SMEM_A = (4 * 256 * 16 + H_ * 32 + V_ * 32 + 32) * (int)sizeof(float)
                       + 16 * (int)sizeof(int);
    cudaFuncSetAttribute(rnn_recur, cudaFuncAttributeMaxDynamicSharedMemorySize, SMEM_A);

    // Slot map (proven): 0=init, 1=dmy1, 2=dmy2, 3=recur (profiled), 4=logits.
    rnn_init<<<(HB + 255) / 256, 256>>>(h0);
    rnn_dmy1<<<1, 32>>>(h0);
    rnn_dmy2<<<1, 32>>>(h0);
    rnn_recur<<<128, THREADS_A, SMEM_A>>>(x, W_xh, W_hh, b_h,
                                          out + (size_t)B_ * S_ * V_);
    rnn_logits<<<(B_ * S_) / 128, 256>>>(W_out, b_out, out);
}